// round 7
// baseline (speedup 1.0000x reference)
#include <cuda_runtime.h>

// Fixed shapes
#define BH_ 64
#define S_  8192
#define D_  64
#define M_  64
#define C_  65
#define TS  128
#define NT  4      // tiles per CTA

__device__ float g_buf1[BH_*M_*C_];

__global__ void zero_buf1_kernel() {
    int i = blockIdx.x*blockDim.x + threadIdx.x;
    if (i < BH_*M_*C_) g_buf1[i] = 0.0f;
}

__device__ __forceinline__ unsigned f2tf(float x) {   // fp32 -> tf32 (RN)
    unsigned r; asm("cvt.rna.tf32.f32 %0, %1;" : "=r"(r) : "f"(x)); return r;
}
__device__ __forceinline__ unsigned smem_u32(const void* p) {
    unsigned a;
    asm("{ .reg .u64 t; cvta.to.shared.u64 t, %1; cvt.u32.u64 %0, t; }" : "=r"(a) : "l"(p));
    return a;
}
__device__ __forceinline__ void cp16(unsigned saddr, const float* g) {
    asm volatile("cp.async.cg.shared.global [%0], [%1], 16;"
                 :: "r"(saddr), "l"(__cvta_generic_to_global(g)));
}
#define CP_COMMIT() asm volatile("cp.async.commit_group;")
#define CP_WAIT1()  asm volatile("cp.async.wait_group 1;")
#define CP_WAIT0()  asm volatile("cp.async.wait_group 0;")

// m16n8k8 tf32 MMA, D += A*B (fp32 accum)
__device__ __forceinline__ void mma8(float* c, const unsigned* a, const unsigned* b) {
    asm volatile("mma.sync.aligned.m16n8k8.row.col.f32.tf32.tf32.f32 "
        "{%0,%1,%2,%3}, {%4,%5,%6,%7}, {%8,%9}, {%0,%1,%2,%3};"
        : "+f"(c[0]), "+f"(c[1]), "+f"(c[2]), "+f"(c[3])
        : "r"(a[0]), "r"(a[1]), "r"(a[2]), "r"(a[3]), "r"(b[0]), "r"(b[1]));
}

// Strides (words)
#define STR_X  76   // raw fp32 X tiles (K/V/Q), cols 0..71 used
#define STR_O  72   // Omega / B1 (tf32)
#define STR_P  68   // feature tile k'/q' (tf32)

// Word offsets, phase K
#define KOF_OM  0u
#define KOF_X0  4608u
#define KOF_X1  (KOF_X0 + 128u*STR_X)
#define KOF_V0  (KOF_X1 + 128u*STR_X)
#define KOF_V1  (KOF_V0 + 128u*STR_X)
#define KOF_P   (KOF_V1 + 128u*STR_X)
#define KOF_HR  (KOF_P  + 128u*STR_P)
#define PK_WORDS (KOF_HR + 128u)

// Word offsets, phase Q
#define QOF_OM  0u
#define QOF_X0  4608u
#define QOF_X1  (QOF_X0 + 128u*STR_X)
#define QOF_P   (QOF_X1 + 128u*STR_X)
#define QOF_B1  (QOF_P  + 128u*STR_P)
#define QOF_HR  (QOF_B1 + 64u*STR_O)
#define PQ_WORDS (QOF_HR + 128u)

// One 128x64 fp32 tile, 8 cp.async per thread (256 threads, coalesced)
__device__ __forceinline__ void issue_tile(const float* g, unsigned sbase, int tid) {
#pragma unroll
    for (int j = 0; j < 8; ++j) {
        int l = j*256 + tid;          // 0..2047 16B-chunks
        int row = l >> 4, ch = l & 15;
        cp16(sbase + (unsigned)(row*STR_X + ch*4)*4u, g + row*64 + ch*4);
    }
}

// Row prefactors: 2 threads per row, shfl-combined
__device__ __forceinline__ void row_h(const float* sX, float* hr, int tid) {
    const int row = tid >> 1, half = tid & 1;
    const float4* rp = (const float4*)(sX + row*STR_X + half*32);
    float ss = 0.f;
#pragma unroll
    for (int j = 0; j < 8; ++j) {
        float4 x = rp[j];
        ss += x.x*x.x + x.y*x.y + x.z*x.z + x.w*x.w;
    }
    ss += __shfl_xor_sync(0xffffffffu, ss, 1);
    if (!half) hr[row] = __expf(-0.5f*ss) * 0.125f;
}

// GEMM1 + exp: sOut[s][m] = tf32( h[s] * exp( sum_d sX[s][d]*sOM[d][m] ) )
// 8 warps; warp w: m16 block w (rows 16w..16w+15) x 64 cols. sX raw fp32.
__device__ __forceinline__ void gemm1_feature(const unsigned* sOM, const float* sX,
                                              const float* hr, unsigned* sOut,
                                              int warp, int lane)
{
    float c[8][4];
#pragma unroll
    for (int nb = 0; nb < 8; ++nb)
#pragma unroll
        for (int q = 0; q < 4; ++q) c[nb][q] = 0.f;

    const int lq = lane >> 2, lr = lane & 3;
    const int row = warp*16 + lq;
#pragma unroll
    for (int k0 = 0; k0 < 8; ++k0) {
        const int kk = k0*8 + lr;
        unsigned a[4];
        a[0] = f2tf(sX[row*STR_X + kk]);
        a[1] = f2tf(sX[(row+8)*STR_X + kk]);
        a[2] = f2tf(sX[row*STR_X + kk + 4]);
        a[3] = f2tf(sX[(row+8)*STR_X + kk + 4]);
#pragma unroll
        for (int nb = 0; nb < 8; ++nb) {
            unsigned b[2];
            int col = nb*8 + lq;
            b[0] = sOM[kk*STR_O + col];
            b[1] = sOM[(kk+4)*STR_O + col];
            mma8(c[nb], a, b);
        }
    }
    const float h0 = hr[row], h8 = hr[row+8];
#pragma unroll
    for (int nb = 0; nb < 8; ++nb) {
        int col = nb*8 + 2*lr;
        sOut[row*STR_P + col]       = f2tf(h0 * __expf(c[nb][0]));
        sOut[row*STR_P + col + 1]   = f2tf(h0 * __expf(c[nb][1]));
        sOut[(row+8)*STR_P + col]   = f2tf(h8 * __expf(c[nb][2]));
        sOut[(row+8)*STR_P + col+1] = f2tf(h8 * __expf(c[nb][3]));
    }
}

// ---------------------------------------------------------------------------
// Phase K: grid (64 heads, 16 splits), 256 threads, NT tiles, cp.async pipeline
// ---------------------------------------------------------------------------
__global__ void __launch_bounds__(256)
pk_kernel(const float* __restrict__ Kg, const float* __restrict__ Vg,
          const float* __restrict__ Og)
{
    extern __shared__ unsigned sm[];
    unsigned* sOM = sm + KOF_OM;
    float*    sXf[2] = { (float*)(sm + KOF_X0), (float*)(sm + KOF_X1) };
    float*    sVf[2] = { (float*)(sm + KOF_V0), (float*)(sm + KOF_V1) };
    unsigned* sVu[2] = { sm + KOF_V0, sm + KOF_V1 };
    unsigned* sP  = sm + KOF_P;
    float*    hr  = (float*)(sm + KOF_HR);
    const unsigned xb[2] = { smem_u32(sm + KOF_X0), smem_u32(sm + KOF_X1) };
    const unsigned vb[2] = { smem_u32(sm + KOF_V0), smem_u32(sm + KOF_V1) };

    const int tid = threadIdx.x, warp = tid >> 5, lane = tid & 31;
    const int lq = lane >> 2, lr = lane & 3;
    const int bh = blockIdx.x, sp = blockIdx.y;

    for (int i = tid; i < D_*M_; i += 256) {
        int d = i >> 6, m = i & 63;
        sOM[d*STR_O + m] = f2tf(Og[i]);
    }
    // V tiles: cols 64..71 constant [1|0...] (1.0f is exact in tf32)
    for (int i = tid; i < 128*8; i += 256) {
        int r = i >> 3, c = 64 + (i & 7);
        float v = (c == 64) ? 1.0f : 0.0f;
        sVf[0][r*STR_X + c] = v;
        sVf[1][r*STR_X + c] = v;
    }

    float acc[9][4];
#pragma unroll
    for (int nb = 0; nb < 9; ++nb)
#pragma unroll
        for (int q = 0; q < 4; ++q) acc[nb][q] = 0.f;

    const size_t base0 = ((size_t)bh*S_ + (size_t)(sp*NT)*TS) * D_;
    issue_tile(Kg + base0, xb[0], tid);
    issue_tile(Vg + base0, vb[0], tid);
    CP_COMMIT();

    for (int t = 0; t < NT; ++t) {
        const int b = t & 1;
        if (t + 1 < NT) {
            const size_t nb_off = base0 + (size_t)(t+1)*TS*D_;
            issue_tile(Kg + nb_off, xb[b^1], tid);
            issue_tile(Vg + nb_off, vb[b^1], tid);
            CP_COMMIT();
            CP_WAIT1();
        } else {
            CP_WAIT0();
        }
        __syncthreads();

        row_h(sXf[b], hr, tid);
        // pre-convert V tile to tf32 in place (disjoint per-thread ranges)
        {
            uint4* vr = (uint4*)(sVf[b] + (tid >> 1)*STR_X + (tid & 1)*32);
#pragma unroll
            for (int j = 0; j < 8; ++j) {
                uint4 w = vr[j];
                w.x = f2tf(__uint_as_float(w.x));
                w.y = f2tf(__uint_as_float(w.y));
                w.z = f2tf(__uint_as_float(w.z));
                w.w = f2tf(__uint_as_float(w.w));
                vr[j] = w;
            }
        }
        __syncthreads();

        gemm1_feature(sOM, sXf[b], hr, sP, warp, lane);
        __syncthreads();

        // GEMM2: acc[m,c] += sum_s k'[s][m]*C[s][c]; warps split the s-range
        const int mblk = warp & 3, khalf = warp >> 2;
        const int m = mblk*16 + lq;
        const unsigned* sV = sVu[b];
#pragma unroll
        for (int k0 = 0; k0 < 8; ++k0) {
            const int kk = khalf*64 + k0*8 + lr;
            unsigned a[4];
            a[0] = sP[kk*STR_P + m];
            a[1] = sP[kk*STR_P + m + 8];
            a[2] = sP[(kk+4)*STR_P + m];
            a[3] = sP[(kk+4)*STR_P + m + 8];
#pragma unroll
            for (int nb = 0; nb < 9; ++nb) {
                unsigned bfr[2];
                int col = nb*8 + lq;
                bfr[0] = sV[kk*STR_X + col];
                bfr[1] = sV[(kk+4)*STR_X + col];
                mma8(acc[nb], a, bfr);
            }
        }
        __syncthreads();   // sP reused next tile
    }

    // Combine the two k-halves through smem (sP is free), then fold to global
    float* red = (float*)sP;
    const int rbase = ((warp & 3)*32 + lane)*36;
    if (warp >= 4) {
#pragma unroll
        for (int nb = 0; nb < 9; ++nb)
#pragma unroll
            for (int q = 0; q < 4; ++q) red[rbase + nb*4 + q] = acc[nb][q];
    }
    __syncthreads();
    if (warp < 4) {
        float* b1 = g_buf1 + (size_t)bh*(M_*C_);
        const int m = warp*16 + lq;
#pragma unroll
        for (int nb = 0; nb < 9; ++nb) {
#pragma unroll
            for (int q = 0; q < 4; ++q) acc[nb][q] += red[rbase + nb*4 + q];
            int col = nb*8 + 2*lr;
            if (col < C_) {
                atomicAdd(&b1[m*C_ + col],     acc[nb][0]);
                atomicAdd(&b1[(m+8)*C_ + col], acc[nb][2]);
            }
            if (col + 1 < C_) {
                atomicAdd(&b1[m*C_ + col + 1],     acc[nb][1]);
                atomicAdd(&b1[(m+8)*C_ + col + 1], acc[nb][3]);
            }
        }
    }
}

// ---------------------------------------------------------------------------
// Phase Q: grid (64 heads, 16 groups), 256 threads, NT tiles, cp.async pipeline
// ---------------------------------------------------------------------------
__global__ void __launch_bounds__(256)
pq_kernel(const float* __restrict__ Qg, float* __restrict__ Out,
          const float* __restrict__ Og)
{
    extern __shared__ unsigned sm[];
    unsigned* sOM = sm + QOF_OM;
    float*    sXf[2] = { (float*)(sm + QOF_X0), (float*)(sm + QOF_X1) };
    unsigned* sP  = sm + QOF_P;
    unsigned* sB1 = sm + QOF_B1;
    float*    hr  = (float*)(sm + QOF_HR);
    const unsigned xb[2] = { smem_u32(sm + QOF_X0), smem_u32(sm + QOF_X1) };

    const int tid = threadIdx.x, warp = tid >> 5, lane = tid & 31;
    const int lq = lane >> 2, lr = lane & 3;
    const int bh = blockIdx.x, sp = blockIdx.y;

    for (int i = tid; i < D_*M_; i += 256) {
        int d = i >> 6, m = i & 63;
        sOM[d*STR_O + m] = f2tf(Og[i]);
    }
    const float* b1g = g_buf1 + (size_t)bh*(M_*C_);
    for (int i = tid; i < M_*STR_O; i += 256) {
        int m = i / STR_O, c = i - m*STR_O;
        sB1[m*STR_O + c] = (c < C_) ? f2tf(b1g[m*C_ + c]) : 0u;
    }

    const size_t base0 = ((size_t)bh*S_ + (size_t)(sp*NT)*TS) * D_;
    issue_tile(Qg + base0, xb[0], tid);
    CP_COMMIT();

    for (int t = 0; t < NT; ++t) {
        const int b = t & 1;
        if (t + 1 < NT) {
            issue_tile(Qg + base0 + (size_t)(t+1)*TS*D_, xb[b^1], tid);
            CP_COMMIT();
            CP_WAIT1();
        } else {
            CP_WAIT0();
        }
        __syncthreads();

        row_h(sXf[b], hr, tid);
        __syncthreads();

        gemm1_feature(sOM, sXf[b], hr, sP, warp, lane);
        __syncthreads();

        // GEMM3: D[128,72] = q' (sP) @ buf1 (sB1); warp w: m16 block w
        float d[9][4];
#pragma unroll
        for (int nb = 0; nb < 9; ++nb)
#pragma unroll
            for (int q = 0; q < 4; ++q) d[nb][q] = 0.f;

        const int row = warp*16 + lq;
#pragma unroll
        for (int k0 = 0; k0 < 8; ++k0) {
            const int kk = k0*8 + lr;
            unsigned a[4];
            a[0] = sP[row*STR_P + kk];
            a[1] = sP[(row+8)*STR_P + kk];
            a[2] = sP[row*STR_P + kk + 4];
            a[3] = sP[(row+8)*STR_P + kk + 4];
#pragma unroll
            for (int nb = 0; nb < 9; ++nb) {
                unsigned bfr[2];
                int col = nb*8 + lq;
                bfr[0] = sB1[kk*STR_O + col];
                bfr[1] = sB1[(kk+4)*STR_O + col];
                mma8(d[nb], a, bfr);
            }
        }

        // divide by denominator (col 64 = nb 8 sub-col 0), stage into X buffer b
        float* stg = sXf[b];
        {
            float den0 = __shfl_sync(0xffffffffu, d[8][0], lane & 28);
            float den8 = __shfl_sync(0xffffffffu, d[8][2], lane & 28);
            float inv0 = 1.0f / den0, inv8 = 1.0f / den8;
#pragma unroll
            for (int nb = 0; nb < 8; ++nb) {
                int col = nb*8 + 2*lr;
                stg[row*STR_X + col]       = d[nb][0]*inv0;
                stg[row*STR_X + col + 1]   = d[nb][1]*inv0;
                stg[(row+8)*STR_X + col]   = d[nb][2]*inv8;
                stg[(row+8)*STR_X + col+1] = d[nb][3]*inv8;
            }
        }
        __syncthreads();

        // coalesced store
        float* ob = Out + base0 + (size_t)t*TS*D_;
        for (int i = tid; i < 2048; i += 256) {
            int r = i >> 4, c4 = i & 15;
            float4 w = *(float4*)&stg[r*STR_X + 4*c4];
            ((float4*)(ob + (size_t)r*D_))[c4] = w;
        }
        __syncthreads();   // stg reused as cp.async dst two tiles later
    }
}

extern "C" void kernel_launch(void* const* d_in, const int* in_sizes, int n_in,
                              void* d_out, int out_size)
{
    const float* Q  = (const float*)d_in[0];
    const float* K  = (const float*)d_in[1];
    const float* V  = (const float*)d_in[2];
    const float* Om = (const float*)d_in[3];
    float* out = (float*)d_out;
    (void)in_sizes; (void)n_in; (void)out_size;

    const int SMEM_K = PK_WORDS * 4;
    const int SMEM_Q = PQ_WORDS * 4;
    cudaFuncSetAttribute(pk_kernel, cudaFuncAttributeMaxDynamicSharedMemorySize, SMEM_K);
    cudaFuncSetAttribute(pq_kernel, cudaFuncAttributeMaxDynamicSharedMemorySize, SMEM_Q);

    zero_buf1_kernel<<<(BH_*M_*C_ + 255)/256, 256>>>();
    pk_kernel<<<dim3(BH_, S_/(TS*NT)), 256, SMEM_K>>>(K, V, Om);
    pq_kernel<<<dim3(BH_, S_/(TS*NT)), 256, SMEM_Q>>>(Q, out, Om);
}

// round 8
// speedup vs baseline: 1.0596x; 1.0596x over previous
#include <cuda_runtime.h>

// Fixed shapes
#define BH_ 64
#define S_  8192
#define D_  64
#define M_  64
#define C_  65
#define TS  128
#define NT  8      // tiles per CTA

__device__ float g_buf1[BH_*M_*C_];

__global__ void zero_buf1_kernel() {
    int i = blockIdx.x*blockDim.x + threadIdx.x;
    if (i < BH_*M_*C_) g_buf1[i] = 0.0f;
}

__device__ __forceinline__ unsigned f2tf(float x) {   // fp32 -> tf32 (RN)
    unsigned r; asm("cvt.rna.tf32.f32 %0, %1;" : "=r"(r) : "f"(x)); return r;
}
__device__ __forceinline__ unsigned smem_u32(const void* p) {
    unsigned a;
    asm("{ .reg .u64 t; cvta.to.shared.u64 t, %1; cvt.u32.u64 %0, t; }" : "=r"(a) : "l"(p));
    return a;
}
__device__ __forceinline__ void cp16(unsigned saddr, const float* g) {
    asm volatile("cp.async.cg.shared.global [%0], [%1], 16;"
                 :: "r"(saddr), "l"(__cvta_generic_to_global(g)));
}
#define CP_COMMIT() asm volatile("cp.async.commit_group;")
#define CP_WAIT1()  asm volatile("cp.async.wait_group 1;")
#define CP_WAIT0()  asm volatile("cp.async.wait_group 0;")

// m16n8k8 tf32 MMA, D += A*B (fp32 accum)
__device__ __forceinline__ void mma8(float* c, const unsigned* a, const unsigned* b) {
    asm volatile("mma.sync.aligned.m16n8k8.row.col.f32.tf32.tf32.f32 "
        "{%0,%1,%2,%3}, {%4,%5,%6,%7}, {%8,%9}, {%0,%1,%2,%3};"
        : "+f"(c[0]), "+f"(c[1]), "+f"(c[2]), "+f"(c[3])
        : "r"(a[0]), "r"(a[1]), "r"(a[2]), "r"(a[3]), "r"(b[0]), "r"(b[1]));
}

// Strides (words)
#define STR_X  76   // raw fp32 X tiles (K/V/Q), cols 0..71 used
#define STR_O  72   // Omega / B1 (tf32)
#define STR_P  68   // feature tile k'/q' (tf32)

// Word offsets, phase K
#define KOF_OM  0u
#define KOF_X0  4608u
#define KOF_X1  (KOF_X0 + 128u*STR_X)
#define KOF_V0  (KOF_X1 + 128u*STR_X)
#define KOF_V1  (KOF_V0 + 128u*STR_X)
#define KOF_P   (KOF_V1 + 128u*STR_X)
#define KOF_HR  (KOF_P  + 128u*STR_P)
#define PK_WORDS (KOF_HR + 128u)

// Word offsets, phase Q
#define QOF_OM  0u
#define QOF_X0  4608u
#define QOF_X1  (QOF_X0 + 128u*STR_X)
#define QOF_P   (QOF_X1 + 128u*STR_X)
#define QOF_B1  (QOF_P  + 128u*STR_P)
#define QOF_HR  (QOF_B1 + 64u*STR_O)
#define PQ_WORDS (QOF_HR + 128u)

// One 128x64 fp32 tile, 8 cp.async per thread (256 threads, coalesced)
__device__ __forceinline__ void issue_tile(const float* g, unsigned sbase, int tid) {
#pragma unroll
    for (int j = 0; j < 8; ++j) {
        int l = j*256 + tid;          // 0..2047 16B-chunks
        int row = l >> 4, ch = l & 15;
        cp16(sbase + (unsigned)(row*STR_X + ch*4)*4u, g + row*64 + ch*4);
    }
}

// Row prefactors: 2 threads per row, shfl-combined
__device__ __forceinline__ void row_h(const float* sX, float* hr, int tid) {
    const int row = tid >> 1, half = tid & 1;
    const float4* rp = (const float4*)(sX + row*STR_X + half*32);
    float ss = 0.f;
#pragma unroll
    for (int j = 0; j < 8; ++j) {
        float4 x = rp[j];
        ss += x.x*x.x + x.y*x.y + x.z*x.z + x.w*x.w;
    }
    ss += __shfl_xor_sync(0xffffffffu, ss, 1);
    if (!half) hr[row] = __expf(-0.5f*ss) * 0.125f;
}

// Hoist omega B fragments for this warp's n-half (loop-invariant).
// bfr[k0][nb][2]: 64 regs.
__device__ __forceinline__ void load_om_frags(const unsigned* sOM, unsigned bfr[8][4][2],
                                              int nh, int lane)
{
    const int lq = lane >> 2, lr = lane & 3;
#pragma unroll
    for (int k0 = 0; k0 < 8; ++k0) {
        const int kk = k0*8 + lr;
#pragma unroll
        for (int nb = 0; nb < 4; ++nb) {
            int col = nh*32 + nb*8 + lq;
            bfr[k0][nb][0] = sOM[kk*STR_O + col];
            bfr[k0][nb][1] = sOM[(kk+4)*STR_O + col];
        }
    }
}

// GEMM1 + exp, 8 warps: warp = (m-block-pair (warp&3), n-half (warp>>2)).
// Rows 32*(warp&3)..+31, cols 32*nh..+31. B from registers, A from raw fp32 smem.
__device__ __forceinline__ void gemm1_feature(const float* sX, const float* hr,
                                              unsigned* sOut, const unsigned bfr[8][4][2],
                                              int warp, int lane)
{
    const int lq = lane >> 2, lr = lane & 3;
    const int mb0 = (warp & 3)*2;
    const int nh  = warp >> 2;

    float c[2][4][4];
#pragma unroll
    for (int mb = 0; mb < 2; ++mb)
#pragma unroll
        for (int nb = 0; nb < 4; ++nb)
#pragma unroll
            for (int q = 0; q < 4; ++q) c[mb][nb][q] = 0.f;

#pragma unroll
    for (int k0 = 0; k0 < 8; ++k0) {
        const int kk = k0*8 + lr;
        unsigned a[2][4];
#pragma unroll
        for (int mb = 0; mb < 2; ++mb) {
            int row = (mb0 + mb)*16 + lq;
            a[mb][0] = f2tf(sX[row*STR_X + kk]);
            a[mb][1] = f2tf(sX[(row+8)*STR_X + kk]);
            a[mb][2] = f2tf(sX[row*STR_X + kk + 4]);
            a[mb][3] = f2tf(sX[(row+8)*STR_X + kk + 4]);
        }
#pragma unroll
        for (int nb = 0; nb < 4; ++nb) {
            mma8(c[0][nb], a[0], bfr[k0][nb]);
            mma8(c[1][nb], a[1], bfr[k0][nb]);
        }
    }
#pragma unroll
    for (int mb = 0; mb < 2; ++mb) {
        int row = (mb0 + mb)*16 + lq;
        float h0 = hr[row], h8 = hr[row+8];
#pragma unroll
        for (int nb = 0; nb < 4; ++nb) {
            int col = nh*32 + nb*8 + 2*lr;
            sOut[row*STR_P + col]       = f2tf(h0 * __expf(c[mb][nb][0]));
            sOut[row*STR_P + col + 1]   = f2tf(h0 * __expf(c[mb][nb][1]));
            sOut[(row+8)*STR_P + col]   = f2tf(h8 * __expf(c[mb][nb][2]));
            sOut[(row+8)*STR_P + col+1] = f2tf(h8 * __expf(c[mb][nb][3]));
        }
    }
}

// ---------------------------------------------------------------------------
// Phase K: grid (64 heads, 8 splits), 256 threads, NT=8 tiles, cp.async pipeline
// ---------------------------------------------------------------------------
__global__ void __launch_bounds__(256)
pk_kernel(const float* __restrict__ Kg, const float* __restrict__ Vg,
          const float* __restrict__ Og)
{
    extern __shared__ unsigned sm[];
    unsigned* sOM = sm + KOF_OM;
    float*    sXf[2] = { (float*)(sm + KOF_X0), (float*)(sm + KOF_X1) };
    float*    sVf[2] = { (float*)(sm + KOF_V0), (float*)(sm + KOF_V1) };
    unsigned* sVu[2] = { sm + KOF_V0, sm + KOF_V1 };
    unsigned* sP  = sm + KOF_P;
    float*    hr  = (float*)(sm + KOF_HR);
    const unsigned xb[2] = { smem_u32(sm + KOF_X0), smem_u32(sm + KOF_X1) };
    const unsigned vb[2] = { smem_u32(sm + KOF_V0), smem_u32(sm + KOF_V1) };

    const int tid = threadIdx.x, warp = tid >> 5, lane = tid & 31;
    const int lq = lane >> 2, lr = lane & 3;
    const int bh = blockIdx.x, sp = blockIdx.y;

    for (int i = tid; i < D_*M_; i += 256) {
        int d = i >> 6, m = i & 63;
        sOM[d*STR_O + m] = f2tf(Og[i]);
    }
    for (int i = tid; i < 128*8; i += 256) {
        int r = i >> 3, c = 64 + (i & 7);
        float v = (c == 64) ? 1.0f : 0.0f;
        sVf[0][r*STR_X + c] = v;
        sVf[1][r*STR_X + c] = v;
    }

    float acc[9][4];
#pragma unroll
    for (int nb = 0; nb < 9; ++nb)
#pragma unroll
        for (int q = 0; q < 4; ++q) acc[nb][q] = 0.f;

    const size_t base0 = ((size_t)bh*S_ + (size_t)(sp*NT)*TS) * D_;
    issue_tile(Kg + base0, xb[0], tid);
    issue_tile(Vg + base0, vb[0], tid);
    CP_COMMIT();
    __syncthreads();

    unsigned bfr[8][4][2];
    load_om_frags(sOM, bfr, warp >> 2, lane);

    for (int t = 0; t < NT; ++t) {
        const int b = t & 1;
        if (t + 1 < NT) {
            const size_t nb_off = base0 + (size_t)(t+1)*TS*D_;
            issue_tile(Kg + nb_off, xb[b^1], tid);
            issue_tile(Vg + nb_off, vb[b^1], tid);
            CP_COMMIT();
            CP_WAIT1();
        } else {
            CP_WAIT0();
        }
        __syncthreads();

        row_h(sXf[b], hr, tid);
        // pre-convert V tile to tf32 in place (disjoint per-thread ranges)
        {
            uint4* vr = (uint4*)(sVf[b] + (tid >> 1)*STR_X + (tid & 1)*32);
#pragma unroll
            for (int j = 0; j < 8; ++j) {
                uint4 w = vr[j];
                w.x = f2tf(__uint_as_float(w.x));
                w.y = f2tf(__uint_as_float(w.y));
                w.z = f2tf(__uint_as_float(w.z));
                w.w = f2tf(__uint_as_float(w.w));
                vr[j] = w;
            }
        }
        __syncthreads();

        gemm1_feature(sXf[b], hr, sP, bfr, warp, lane);
        __syncthreads();

        // GEMM2: acc[m,c] += sum_s k'[s][m]*C[s][c]; warps split the s-range
        const int m = (warp & 3)*16 + lq;
        const int khalf = warp >> 2;
        const unsigned* sV = sVu[b];
#pragma unroll
        for (int k0 = 0; k0 < 8; ++k0) {
            const int kk = khalf*64 + k0*8 + lr;
            unsigned a[4];
            a[0] = sP[kk*STR_P + m];
            a[1] = sP[kk*STR_P + m + 8];
            a[2] = sP[(kk+4)*STR_P + m];
            a[3] = sP[(kk+4)*STR_P + m + 8];
#pragma unroll
            for (int nb = 0; nb < 9; ++nb) {
                unsigned bv[2];
                int col = nb*8 + lq;
                bv[0] = sV[kk*STR_X + col];
                bv[1] = sV[(kk+4)*STR_X + col];
                mma8(acc[nb], a, bv);
            }
        }
        __syncthreads();   // sP reused next tile
    }

    // Combine the two k-halves through smem (sP is free), then fold to global
    float* red = (float*)sP;
    const int rbase = ((warp & 3)*32 + lane)*36;
    if (warp >= 4) {
#pragma unroll
        for (int nb = 0; nb < 9; ++nb)
#pragma unroll
            for (int q = 0; q < 4; ++q) red[rbase + nb*4 + q] = acc[nb][q];
    }
    __syncthreads();
    if (warp < 4) {
        float* b1 = g_buf1 + (size_t)bh*(M_*C_);
        const int m = warp*16 + lq;
#pragma unroll
        for (int nb = 0; nb < 9; ++nb) {
#pragma unroll
            for (int q = 0; q < 4; ++q) acc[nb][q] += red[rbase + nb*4 + q];
            int col = nb*8 + 2*lr;
            if (col < C_) {
                atomicAdd(&b1[m*C_ + col],     acc[nb][0]);
                atomicAdd(&b1[(m+8)*C_ + col], acc[nb][2]);
            }
            if (col + 1 < C_) {
                atomicAdd(&b1[m*C_ + col + 1],     acc[nb][1]);
                atomicAdd(&b1[(m+8)*C_ + col + 1], acc[nb][3]);
            }
        }
    }
}

// ---------------------------------------------------------------------------
// Phase Q: grid (64 heads, 8 groups), 256 threads, NT=8 tiles, cp.async pipeline
// ---------------------------------------------------------------------------
__global__ void __launch_bounds__(256)
pq_kernel(const float* __restrict__ Qg, float* __restrict__ Out,
          const float* __restrict__ Og)
{
    extern __shared__ unsigned sm[];
    unsigned* sOM = sm + QOF_OM;
    float*    sXf[2] = { (float*)(sm + QOF_X0), (float*)(sm + QOF_X1) };
    unsigned* sP  = sm + QOF_P;
    unsigned* sB1 = sm + QOF_B1;
    float*    hr  = (float*)(sm + QOF_HR);
    const unsigned xb[2] = { smem_u32(sm + QOF_X0), smem_u32(sm + QOF_X1) };

    const int tid = threadIdx.x, warp = tid >> 5, lane = tid & 31;
    const int lq = lane >> 2, lr = lane & 3;
    const int bh = blockIdx.x, sp = blockIdx.y;

    for (int i = tid; i < D_*M_; i += 256) {
        int d = i >> 6, m = i & 63;
        sOM[d*STR_O + m] = f2tf(Og[i]);
    }
    const float* b1g = g_buf1 + (size_t)bh*(M_*C_);
    for (int i = tid; i < M_*STR_O; i += 256) {
        int m = i / STR_O, c = i - m*STR_O;
        sB1[m*STR_O + c] = (c < C_) ? f2tf(b1g[m*C_ + c]) : 0u;
    }

    const size_t base0 = ((size_t)bh*S_ + (size_t)(sp*NT)*TS) * D_;
    issue_tile(Qg + base0, xb[0], tid);
    CP_COMMIT();
    __syncthreads();

    unsigned bfr[8][4][2];
    load_om_frags(sOM, bfr, warp >> 2, lane);

    for (int t = 0; t < NT; ++t) {
        const int b = t & 1;
        if (t + 1 < NT) {
            issue_tile(Qg + base0 + (size_t)(t+1)*TS*D_, xb[b^1], tid);
            CP_COMMIT();
            CP_WAIT1();
        } else {
            CP_WAIT0();
        }
        __syncthreads();

        row_h(sXf[b], hr, tid);
        __syncthreads();

        gemm1_feature(sXf[b], hr, sP, bfr, warp, lane);
        __syncthreads();

        // GEMM3: D[128,72] = q' (sP) @ buf1 (sB1); warp w: m16 block w
        float d[9][4];
#pragma unroll
        for (int nb = 0; nb < 9; ++nb)
#pragma unroll
            for (int q = 0; q < 4; ++q) d[nb][q] = 0.f;

        const int row = warp*16 + lq;
#pragma unroll
        for (int k0 = 0; k0 < 8; ++k0) {
            const int kk = k0*8 + lr;
            unsigned a[4];
            a[0] = sP[row*STR_P + kk];
            a[1] = sP[(row+8)*STR_P + kk];
            a[2] = sP[row*STR_P + kk + 4];
            a[3] = sP[(row+8)*STR_P + kk + 4];
#pragma unroll
            for (int nb = 0; nb < 9; ++nb) {
                unsigned bv[2];
                int col = nb*8 + lq;
                bv[0] = sB1[kk*STR_O + col];
                bv[1] = sB1[(kk+4)*STR_O + col];
                mma8(d[nb], a, bv);
            }
        }

        // divide by denominator (col 64 = nb 8 sub-col 0), stage into X buffer b
        float* stg = sXf[b];
        {
            float den0 = __shfl_sync(0xffffffffu, d[8][0], lane & 28);
            float den8 = __shfl_sync(0xffffffffu, d[8][2], lane & 28);
            float inv0 = 1.0f / den0, inv8 = 1.0f / den8;
#pragma unroll
            for (int nb = 0; nb < 8; ++nb) {
                int col = nb*8 + 2*lr;
                stg[row*STR_X + col]       = d[nb][0]*inv0;
                stg[row*STR_X + col + 1]   = d[nb][1]*inv0;
                stg[(row+8)*STR_X + col]   = d[nb][2]*inv8;
                stg[(row+8)*STR_X + col+1] = d[nb][3]*inv8;
            }
        }
        __syncthreads();

        // coalesced store
        float* ob = Out + base0 + (size_t)t*TS*D_;
        for (int i = tid; i < 2048; i += 256) {
            int r = i >> 4, c4 = i & 15;
            float4 w = *(float4*)&stg[r*STR_X + 4*c4];
            ((float4*)(ob + (size_t)r*D_))[c4] = w;
        }
        __syncthreads();   // stg reused as cp.async dst two tiles later
    }
}

extern "C" void kernel_launch(void* const* d_in, const int* in_sizes, int n_in,
                              void* d_out, int out_size)
{
    const float* Q  = (const float*)d_in[0];
    const float* K  = (const float*)d_in[1];
    const float* V  = (const float*)d_in[2];
    const float* Om = (const float*)d_in[3];
    float* out = (float*)d_out;
    (void)in_sizes; (void)n_in; (void)out_size;

    const int SMEM_K = PK_WORDS * 4;
    const int SMEM_Q = PQ_WORDS * 4;
    cudaFuncSetAttribute(pk_kernel, cudaFuncAttributeMaxDynamicSharedMemorySize, SMEM_K);
    cudaFuncSetAttribute(pq_kernel, cudaFuncAttributeMaxDynamicSharedMemorySize, SMEM_Q);

    zero_buf1_kernel<<<(BH_*M_*C_ + 255)/256, 256>>>();
    pk_kernel<<<dim3(BH_, S_/(TS*NT)), 256, SMEM_K>>>(K, V, Om);
    pq_kernel<<<dim3(BH_, S_/(TS*NT)), 256, SMEM_Q>>>(Q, out, Om);
}

// round 9
// speedup vs baseline: 1.6685x; 1.5746x over previous
#include <cuda_runtime.h>
#include <cuda_fp16.h>

// Fixed shapes
#define BH_ 64
#define S_  8192
#define D_  64
#define M_  64
#define C_  65
#define TS  128
#define NT  8      // tiles per CTA

__device__ float g_buf1[BH_*M_*C_];

__global__ void zero_buf1_kernel() {
    int i = blockIdx.x*blockDim.x + threadIdx.x;
    if (i < BH_*M_*C_) g_buf1[i] = 0.0f;
}

__device__ __forceinline__ unsigned pack_h2(float lo, float hi) {
    __half2 h = __floats2half2_rn(lo, hi);   // x = lo, y = hi
    return *reinterpret_cast<unsigned*>(&h);
}
__device__ __forceinline__ unsigned smem_u32(const void* p) {
    unsigned a;
    asm("{ .reg .u64 t; cvta.to.shared.u64 t, %1; cvt.u32.u64 %0, t; }" : "=r"(a) : "l"(p));
    return a;
}
__device__ __forceinline__ void cp16(unsigned saddr, const float* g) {
    asm volatile("cp.async.cg.shared.global [%0], [%1], 16;"
                 :: "r"(saddr), "l"(__cvta_generic_to_global(g)));
}
#define CP_COMMIT() asm volatile("cp.async.commit_group;")
#define CP_WAIT1()  asm volatile("cp.async.wait_group 1;")
#define CP_WAIT0()  asm volatile("cp.async.wait_group 0;")

// m16n8k16 fp16 MMA, fp32 accumulate, D += A*B
__device__ __forceinline__ void mmaf16(float* c, const unsigned* a, const unsigned* b) {
    asm volatile("mma.sync.aligned.m16n8k16.row.col.f32.f16.f16.f32 "
        "{%0,%1,%2,%3}, {%4,%5,%6,%7}, {%8,%9}, {%0,%1,%2,%3};"
        : "+f"(c[0]), "+f"(c[1]), "+f"(c[2]), "+f"(c[3])
        : "r"(a[0]), "r"(a[1]), "r"(a[2]), "r"(a[3]), "r"(b[0]), "r"(b[1]));
}

// Strides (32-bit words)
#define STRX 72   // raw fp32 tiles (K/V/Q), 64 cols + pad; 72%4==0 (float4 rows)
#define STRO 36   // half2-packed [.][32] arrays: omTh, qPh, B1h
#define STRT 68   // half2-packed [.][64] arrays: kTh, VTh

// Phase K word offsets
#define KOF_OM 0u
#define KOF_HR 2304u
#define KOF_X0 2432u
#define KOF_X1 (KOF_X0 + 128u*STRX)
#define KOF_V0 (KOF_X1 + 128u*STRX)
#define KOF_V1 (KOF_V0 + 128u*STRX)
#define KOF_KT (KOF_V1 + 128u*STRX)          // [64][68]
#define KOF_VT (KOF_KT + 64u*STRT)           // [72][68]
#define PK_WORDS (KOF_VT + 72u*STRT)         // 48544 words = 194176 B

// Phase Q word offsets
#define QOF_OM 0u
#define QOF_HR 2304u
#define QOF_X0 2432u
#define QOF_X1 (QOF_X0 + 128u*STRX)
#define QOF_QP (QOF_X1 + 128u*STRX)          // [128][36]
#define QOF_B1 (QOF_QP + 128u*STRO)          // [72][36]
#define PQ_WORDS (QOF_B1 + 72u*STRO)         // 28064 words = 112256 B -> 2 CTAs/SM

// One 128x64 fp32 tile, 16 cp.async per thread (128 threads, coalesced)
__device__ __forceinline__ void issue_tile(const float* g, unsigned sbase, int tid) {
#pragma unroll
    for (int j = 0; j < 16; ++j) {
        int l = j*128 + tid;
        int row = l >> 4, ch = l & 15;
        cp16(sbase + (unsigned)(row*STRX + ch*4)*4u, g + row*64 + ch*4);
    }
}

// omTh[m][j] = half2{ Om[2j][m], Om[2j+1][m] }  (omega is [d][m] row-major)
__device__ __forceinline__ void setup_om(unsigned* sOM, const float* Og, int tid) {
    for (int i = tid; i < 2048; i += 128) {
        int m = i >> 5, j = i & 31;
        sOM[m*STRO + j] = pack_h2(Og[(2*j)*64 + m], Og[(2*j+1)*64 + m]);
    }
}

// ---------------------------------------------------------------------------
// Phase K: grid (64, 8), 128 threads. Per tile:
//   GEMM1^T: proj^T[m][s] = Omega^T x X^T (fp16 MMA)  -> k'^T packed half2
//   GEMM2:   buf1[m][c] += k'^T x V (V^T built by 16-bit scatter)
// ---------------------------------------------------------------------------
__global__ void __launch_bounds__(128)
pk_kernel(const float* __restrict__ Kg, const float* __restrict__ Vg,
          const float* __restrict__ Og)
{
    extern __shared__ unsigned sm[];
    unsigned* sOM = sm + KOF_OM;
    float*    hr  = (float*)(sm + KOF_HR);
    float*    sX[2] = { (float*)(sm + KOF_X0), (float*)(sm + KOF_X1) };
    float*    sV[2] = { (float*)(sm + KOF_V0), (float*)(sm + KOF_V1) };
    unsigned* kT = sm + KOF_KT;
    unsigned* vT = sm + KOF_VT;
    const unsigned xb[2] = { smem_u32(sm + KOF_X0), smem_u32(sm + KOF_X1) };
    const unsigned vb[2] = { smem_u32(sm + KOF_V0), smem_u32(sm + KOF_V1) };

    const int tid = threadIdx.x, w = tid >> 5, lane = tid & 31;
    const int gr = lane >> 2, tg = lane & 3;
    const int bh = blockIdx.x, sp = blockIdx.y;

    setup_om(sOM, Og, tid);
    // VT constant rows: c=64 ones, c=65..71 zeros
    for (int i = tid; i < 8*STRT; i += 128) {
        int r = i / STRT, jj = i - r*STRT;
        vT[(64 + r)*STRT + jj] = (r == 0) ? 0x3C003C00u : 0u;
    }

    float acc[9][4];
#pragma unroll
    for (int nb = 0; nb < 9; ++nb)
#pragma unroll
        for (int q = 0; q < 4; ++q) acc[nb][q] = 0.f;

    const size_t base0 = ((size_t)bh*S_ + (size_t)(sp*NT)*TS) * D_;
    issue_tile(Kg + base0, xb[0], tid);
    issue_tile(Vg + base0, vb[0], tid);
    CP_COMMIT();

    for (int t = 0; t < NT; ++t) {
        const int b = t & 1;
        if (t + 1 < NT) {
            const size_t noff = base0 + (size_t)(t+1)*TS*D_;
            issue_tile(Kg + noff, xb[b^1], tid);
            issue_tile(Vg + noff, vb[b^1], tid);
            CP_COMMIT();
            CP_WAIT1();
        } else {
            CP_WAIT0();
        }
        __syncthreads();

        // row prefactor h (thread = row)
        {
            const float4* rp = (const float4*)(sX[b] + tid*STRX);
            float ss = 0.f;
#pragma unroll
            for (int j = 0; j < 16; ++j) {
                float4 x = rp[j];
                ss += x.x*x.x + x.y*x.y + x.z*x.z + x.w*x.w;
            }
            hr[tid] = __expf(-0.5f*ss) * 0.125f;
        }
        // V^T scatter: vTh[c][s] halves (sub-word writes, conflict-free)
        {
            const float4* vp = (const float4*)(sV[b] + tid*STRX);
            __half* vh = (__half*)vT;
#pragma unroll
            for (int j = 0; j < 16; ++j) {
                float4 v = vp[j];
                vh[(4*j+0)*(2*STRT) + tid] = __float2half_rn(v.x);
                vh[(4*j+1)*(2*STRT) + tid] = __float2half_rn(v.y);
                vh[(4*j+2)*(2*STRT) + tid] = __float2half_rn(v.z);
                vh[(4*j+3)*(2*STRT) + tid] = __float2half_rn(v.w);
            }
        }
        __syncthreads();

        // GEMM1^T: D[m=64][s=128], warp w owns s-cols 32w..32w+31 (4 n8 blocks)
        float c1[4][4][4];
#pragma unroll
        for (int mb = 0; mb < 4; ++mb)
#pragma unroll
            for (int nb = 0; nb < 4; ++nb)
#pragma unroll
                for (int q = 0; q < 4; ++q) c1[mb][nb][q] = 0.f;

#pragma unroll
        for (int kst = 0; kst < 4; ++kst) {
            unsigned a[4][4];
#pragma unroll
            for (int mb = 0; mb < 4; ++mb) {
                a[mb][0] = sOM[(mb*16+gr)*STRO   + kst*8 + tg];
                a[mb][1] = sOM[(mb*16+gr+8)*STRO + kst*8 + tg];
                a[mb][2] = sOM[(mb*16+gr)*STRO   + kst*8 + 4 + tg];
                a[mb][3] = sOM[(mb*16+gr+8)*STRO + kst*8 + 4 + tg];
            }
#pragma unroll
            for (int nb = 0; nb < 4; ++nb) {
                int s = w*32 + nb*8 + gr;
                float2 x0 = *(const float2*)(sX[b] + s*STRX + kst*16 + 2*tg);
                float2 x1 = *(const float2*)(sX[b] + s*STRX + kst*16 + 2*tg + 8);
                unsigned bb[2] = { pack_h2(x0.x, x0.y), pack_h2(x1.x, x1.y) };
#pragma unroll
                for (int mb = 0; mb < 4; ++mb) mmaf16(c1[mb][nb], a[mb], bb);
            }
        }
        // k' = h * exp(proj): thread holds s-pairs -> pack into kTh[m][s/2]
#pragma unroll
        for (int nb = 0; nb < 4; ++nb) {
            int s0 = w*32 + nb*8 + 2*tg;
            float h0 = hr[s0], h1 = hr[s0+1];
            int spx = w*16 + nb*4 + tg;
#pragma unroll
            for (int mb = 0; mb < 4; ++mb) {
                int m = mb*16 + gr;
                kT[m*STRT + spx]     = pack_h2(h0*__expf(c1[mb][nb][0]), h1*__expf(c1[mb][nb][1]));
                kT[(m+8)*STRT + spx] = pack_h2(h0*__expf(c1[mb][nb][2]), h1*__expf(c1[mb][nb][3]));
            }
        }
        __syncthreads();

        // GEMM2: acc[m16 of warp][c=72] += k'^T x V over s=128 (8 k16 steps)
#pragma unroll
        for (int kst = 0; kst < 8; ++kst) {
            unsigned a[4];
            a[0] = kT[(w*16+gr)*STRT   + kst*8 + tg];
            a[1] = kT[(w*16+gr+8)*STRT + kst*8 + tg];
            a[2] = kT[(w*16+gr)*STRT   + kst*8 + 4 + tg];
            a[3] = kT[(w*16+gr+8)*STRT + kst*8 + 4 + tg];
#pragma unroll
            for (int nb = 0; nb < 9; ++nb) {
                unsigned bb[2] = { vT[(nb*8+gr)*STRT + kst*8 + tg],
                                   vT[(nb*8+gr)*STRT + kst*8 + 4 + tg] };
                mmaf16(acc[nb], a, bb);
            }
        }
        __syncthreads();   // kT / vT reused next tile
    }

    // Fold into global buf1
    float* b1 = g_buf1 + (size_t)bh*(M_*C_);
    const int m = w*16 + gr;
#pragma unroll
    for (int nb = 0; nb < 9; ++nb) {
        int col = nb*8 + 2*tg;
        if (col < C_) {
            atomicAdd(&b1[m*C_ + col],     acc[nb][0]);
            atomicAdd(&b1[(m+8)*C_ + col], acc[nb][2]);
        }
        if (col + 1 < C_) {
            atomicAdd(&b1[m*C_ + col + 1],     acc[nb][1]);
            atomicAdd(&b1[(m+8)*C_ + col + 1], acc[nb][3]);
        }
    }
}

// ---------------------------------------------------------------------------
// Phase Q: grid (64, 8), 128 threads, 2 CTAs/SM.
//   GEMM1: q'[s][m] (m-pairs in fragment -> local half2 pack)
//   GEMM3: D[s][c] = q' x buf1 (B1 transposed+packed at setup), divide, store
// ---------------------------------------------------------------------------
__global__ void __launch_bounds__(128)
pq_kernel(const float* __restrict__ Qg, float* __restrict__ Out,
          const float* __restrict__ Og)
{
    extern __shared__ unsigned sm[];
    unsigned* sOM = sm + QOF_OM;
    float*    hr  = (float*)(sm + QOF_HR);
    float*    sX[2] = { (float*)(sm + QOF_X0), (float*)(sm + QOF_X1) };
    unsigned* qP = sm + QOF_QP;
    unsigned* sB1 = sm + QOF_B1;
    const unsigned xb[2] = { smem_u32(sm + QOF_X0), smem_u32(sm + QOF_X1) };

    const int tid = threadIdx.x, w = tid >> 5, lane = tid & 31;
    const int gr = lane >> 2, tg = lane & 3;
    const int bh = blockIdx.x, sp = blockIdx.y;

    setup_om(sOM, Og, tid);
    // B1h[c][j] = half2{ buf1[2j][c], buf1[2j+1][c] }; c>=65 zero
    const float* b1g = g_buf1 + (size_t)bh*(M_*C_);
    for (int i = tid; i < 72*32; i += 128) {
        int c = i >> 5, j = i & 31;
        unsigned v = 0u;
        if (c < C_) v = pack_h2(b1g[(2*j)*C_ + c], b1g[(2*j+1)*C_ + c]);
        sB1[c*STRO + j] = v;
    }

    const size_t base0 = ((size_t)bh*S_ + (size_t)(sp*NT)*TS) * D_;
    issue_tile(Qg + base0, xb[0], tid);
    CP_COMMIT();

    for (int t = 0; t < NT; ++t) {
        const int b = t & 1;
        if (t + 1 < NT) {
            issue_tile(Qg + base0 + (size_t)(t+1)*TS*D_, xb[b^1], tid);
            CP_COMMIT();
            CP_WAIT1();
        } else {
            CP_WAIT0();
        }
        __syncthreads();

        {
            const float4* rp = (const float4*)(sX[b] + tid*STRX);
            float ss = 0.f;
#pragma unroll
            for (int j = 0; j < 16; ++j) {
                float4 x = rp[j];
                ss += x.x*x.x + x.y*x.y + x.z*x.z + x.w*x.w;
            }
            hr[tid] = __expf(-0.5f*ss) * 0.125f;
        }
        __syncthreads();

        // GEMM1: D[s=128][m=64]; warp w rows 32w..32w+31 (2 m16 blocks)
        {
            float cq[2][8][4];
#pragma unroll
            for (int mb = 0; mb < 2; ++mb)
#pragma unroll
                for (int nb = 0; nb < 8; ++nb)
#pragma unroll
                    for (int q = 0; q < 4; ++q) cq[mb][nb][q] = 0.f;

#pragma unroll
            for (int kst = 0; kst < 4; ++kst) {
                unsigned a[2][4];
#pragma unroll
                for (int mb = 0; mb < 2; ++mb) {
                    int row = w*32 + mb*16 + gr;
                    float2 p0 = *(const float2*)(sX[b] + row*STRX     + kst*16 + 2*tg);
                    float2 p1 = *(const float2*)(sX[b] + (row+8)*STRX + kst*16 + 2*tg);
                    float2 p2 = *(const float2*)(sX[b] + row*STRX     + kst*16 + 2*tg + 8);
                    float2 p3 = *(const float2*)(sX[b] + (row+8)*STRX + kst*16 + 2*tg + 8);
                    a[mb][0] = pack_h2(p0.x, p0.y);
                    a[mb][1] = pack_h2(p1.x, p1.y);
                    a[mb][2] = pack_h2(p2.x, p2.y);
                    a[mb][3] = pack_h2(p3.x, p3.y);
                }
#pragma unroll
                for (int nb = 0; nb < 8; ++nb) {
                    unsigned bb[2] = { sOM[(nb*8+gr)*STRO + kst*8 + tg],
                                       sOM[(nb*8+gr)*STRO + kst*8 + 4 + tg] };
                    mmaf16(cq[0][nb], a[0], bb);
                    mmaf16(cq[1][nb], a[1], bb);
                }
            }
            // q' = h * exp: m-pairs -> qP[s][m/2]
#pragma unroll
            for (int mb = 0; mb < 2; ++mb) {
                int row = w*32 + mb*16 + gr;
                float h0 = hr[row], h8 = hr[row+8];
#pragma unroll
                for (int nb = 0; nb < 8; ++nb) {
                    int mp = nb*4 + tg;
                    qP[row*STRO + mp]     = pack_h2(h0*__expf(cq[mb][nb][0]), h0*__expf(cq[mb][nb][1]));
                    qP[(row+8)*STRO + mp] = pack_h2(h8*__expf(cq[mb][nb][2]), h8*__expf(cq[mb][nb][3]));
                }
            }
        }
        __syncthreads();

        // GEMM3: D[s][c=72] = q' x buf1 over m=64 (4 k16 steps)
        float dq[2][9][4];
#pragma unroll
        for (int mb = 0; mb < 2; ++mb)
#pragma unroll
            for (int nb = 0; nb < 9; ++nb)
#pragma unroll
                for (int q = 0; q < 4; ++q) dq[mb][nb][q] = 0.f;

#pragma unroll
        for (int kst = 0; kst < 4; ++kst) {
            unsigned a[2][4];
#pragma unroll
            for (int mb = 0; mb < 2; ++mb) {
                int row = w*32 + mb*16 + gr;
                a[mb][0] = qP[row*STRO     + kst*8 + tg];
                a[mb][1] = qP[(row+8)*STRO + kst*8 + tg];
                a[mb][2] = qP[row*STRO     + kst*8 + 4 + tg];
                a[mb][3] = qP[(row+8)*STRO + kst*8 + 4 + tg];
            }
#pragma unroll
            for (int nb = 0; nb < 9; ++nb) {
                unsigned bb[2] = { sB1[(nb*8+gr)*STRO + kst*8 + tg],
                                   sB1[(nb*8+gr)*STRO + kst*8 + 4 + tg] };
                mmaf16(dq[0][nb], a[0], bb);
                mmaf16(dq[1][nb], a[1], bb);
            }
        }

        // divide by denominator (c=64: nb=8, subcol 0), stage fp32 into sX[b]
        float* stg = sX[b];
#pragma unroll
        for (int mb = 0; mb < 2; ++mb) {
            int row = w*32 + mb*16 + gr;
            float den0 = __shfl_sync(0xffffffffu, dq[mb][8][0], lane & 28);
            float den8 = __shfl_sync(0xffffffffu, dq[mb][8][2], lane & 28);
            float inv0 = 1.0f / den0, inv8 = 1.0f / den8;
#pragma unroll
            for (int nb = 0; nb < 8; ++nb) {
                int col = nb*8 + 2*tg;
                stg[row*STRX + col]       = dq[mb][nb][0]*inv0;
                stg[row*STRX + col + 1]   = dq[mb][nb][1]*inv0;
                stg[(row+8)*STRX + col]   = dq[mb][nb][2]*inv8;
                stg[(row+8)*STRX + col+1] = dq[mb][nb][3]*inv8;
            }
        }
        __syncthreads();

        // coalesced store 128x64
        float* ob = Out + base0 + (size_t)t*TS*D_;
        for (int i = tid; i < 2048; i += 128) {
            int r = i >> 4, c4 = i & 15;
            float4 v = *(float4*)&stg[r*STRX + 4*c4];
            ((float4*)(ob + (size_t)r*D_))[c4] = v;
        }
        __syncthreads();   // stg reused as cp.async dst two tiles later
    }
}

extern "C" void kernel_launch(void* const* d_in, const int* in_sizes, int n_in,
                              void* d_out, int out_size)
{
    const float* Q  = (const float*)d_in[0];
    const float* K  = (const float*)d_in[1];
    const float* V  = (const float*)d_in[2];
    const float* Om = (const float*)d_in[3];
    float* out = (float*)d_out;
    (void)in_sizes; (void)n_in; (void)out_size;

    const int SMEM_K = PK_WORDS * 4;
    const int SMEM_Q = PQ_WORDS * 4;
    cudaFuncSetAttribute(pk_kernel, cudaFuncAttributeMaxDynamicSharedMemorySize, SMEM_K);
    cudaFuncSetAttribute(pq_kernel, cudaFuncAttributeMaxDynamicSharedMemorySize, SMEM_Q);

    zero_buf1_kernel<<<(BH_*M_*C_ + 255)/256, 256>>>();
    pk_kernel<<<dim3(BH_, S_/(TS*NT)), 128, SMEM_K>>>(K, V, Om);
    pq_kernel<<<dim3(BH_, S_/(TS*NT)), 128, SMEM_Q>>>(Q, out, Om);
}